// round 5
// baseline (speedup 1.0000x reference)
#include <cuda_runtime.h>
#include <cuda_bf16.h>
#include <stdint.h>

#define NROWS 16384
#define DIM   768
#define NLAT  5000
#define NLATP 5120
#define CHARS 8

// ---- GEMM tiling ----
#define BM 128
#define BN 64
#define BK 16

typedef unsigned long long ull;

// ---------------- scratch (static __device__) ----------------
__device__ int g_is64;
__device__ __align__(128) float g_Lf [(size_t)NLATP * DIM];   // latent fp32 [5120,768], pad rows 0
__device__ __align__(128) float g_LTf[(size_t)DIM * NLATP];   // latent^T fp32 [768,5120], pad cols 0
__device__ __align__(128) float g_E  [(size_t)NROWS * DIM];   // lang_emb fp32
__device__ __align__(128) float g_S  [(size_t)NROWS * NLATP]; // scores fp32
__device__ __align__(128) float g_D  [(size_t)NROWS * NLATP]; // softmax dist fp32 (pad cols 0)

// packed f32x2 FMA: d = a*b + d (elementwise on 2 packed floats)
#define FMA2(d, a, b) \
    asm("fma.rn.f32x2 %0, %1, %2, %0;" : "+l"(d) : "l"(a), "l"(b))

__device__ __forceinline__ float f2lo(ull v) { return __uint_as_float((uint32_t)v); }
__device__ __forceinline__ float f2hi(ull v) { return __uint_as_float((uint32_t)(v >> 32)); }

// ---------------- small kernels ----------------
__global__ void detect_kernel(const int* __restrict__ x32) {
    if (threadIdx.x == 0 && blockIdx.x == 0) {
        int is64 = 1;
        for (int i = 1; i < 128; i += 2)
            if (x32[i] != 0) { is64 = 0; break; }
        g_is64 = is64;
    }
}

__global__ void conv_latent_kernel(const float* __restrict__ L) {
    int idx = blockIdx.x * 256 + threadIdx.x;
    if (idx < NLATP * DIM) {
        int r = idx / DIM;
        g_Lf[idx] = (r < NLAT) ? L[idx] : 0.0f;
    }
}

// g_LTf[d, k] = L[k, d], zero pad for k >= NLAT.  block(32,8), grid(160, 24)
__global__ void transpose_latent_kernel(const float* __restrict__ L) {
    __shared__ float t[32][33];
    int k0 = blockIdx.x * 32, d0 = blockIdx.y * 32;
    #pragma unroll
    for (int i = 0; i < 4; i++) {
        int k = k0 + threadIdx.y + 8 * i;
        t[threadIdx.y + 8 * i][threadIdx.x] =
            (k < NLAT) ? L[(size_t)k * DIM + d0 + threadIdx.x] : 0.0f;
    }
    __syncthreads();
    #pragma unroll
    for (int i = 0; i < 4; i++) {
        int d = d0 + threadIdx.y + 8 * i;
        g_LTf[(size_t)d * NLATP + k0 + threadIdx.x] = t[threadIdx.x][threadIdx.y + 8 * i];
    }
}

__global__ void embed_kernel(const void* __restrict__ xv, const float* __restrict__ ce) {
    __shared__ int ids[CHARS];
    __shared__ float s_inv;
    int n = blockIdx.x;
    if (threadIdx.x < CHARS) {
        int id;
        if (g_is64) id = (int)((const long long*)xv)[(size_t)n * CHARS + threadIdx.x];
        else        id = ((const int*)xv)[(size_t)n * CHARS + threadIdx.x];
        ids[threadIdx.x] = id;
    }
    __syncthreads();
    if (threadIdx.x == 0) {
        int c = 0;
        #pragma unroll
        for (int i = 0; i < CHARS; i++) c += (ids[i] != 0);
        if (c < 1) c = 1;
        s_inv = 1.0f / (float)c;
    }
    __syncthreads();
    float inv = s_inv;
    for (int d = threadIdx.x; d < DIM; d += 256) {
        float s = 0.0f;
        #pragma unroll
        for (int c = 0; c < CHARS; c++) {
            int id = ids[c];
            if (id != 0) s += ce[(size_t)id * DIM + d];
        }
        g_E[(size_t)n * DIM + d] = tanhf(s * inv);
    }
}

__global__ void softmax_kernel() {
    __shared__ float sc[NLAT];
    __shared__ float red[256];
    int n = blockIdx.x, t = threadIdx.x;
    const float* s = g_S + (size_t)n * NLATP;

    float m = -1e30f;
    for (int i = t; i < NLAT; i += 256) { float v = s[i]; sc[i] = v; m = fmaxf(m, v); }
    red[t] = m; __syncthreads();
    for (int off = 128; off; off >>= 1) {
        if (t < off) red[t] = fmaxf(red[t], red[t + off]);
        __syncthreads();
    }
    m = red[0]; __syncthreads();

    float sum = 0.0f;
    for (int i = t; i < NLAT; i += 256) sum += __expf(sc[i] - m);
    red[t] = sum; __syncthreads();
    for (int off = 128; off; off >>= 1) {
        if (t < off) red[t] += red[t + off];
        __syncthreads();
    }
    float inv = 1.0f / red[0];

    float* d = g_D + (size_t)n * NLATP;
    for (int i = t; i < NLAT; i += 256) d[i] = __expf(sc[i] - m) * inv;
    for (int i = NLAT + t; i < NLATP; i += 256) d[i] = 0.0f;
}

// ---------------- f32x2 SIMT GEMM ----------------
// C[BM,BN] = A[M,K] * B[N,K]^T (both row-major fp32, K-major)
// Thread tile 8m x 4n; m-pairs packed into f32x2, B duplicated (b,b) in smem.
// mode 1: C -> g_S
// mode 2: out = g_E + C with special-token override
__global__ __launch_bounds__(256, 2) void gemm_f32(
    const float* __restrict__ A, size_t lda,
    const float* __restrict__ B, size_t ldb,
    int nchunks, int mode,
    const void* __restrict__ xv, const float* __restrict__ ce,
    float* __restrict__ out)
{
    __shared__ float As[2][BK][BM];        // col-major within tile: [k][m]
    __shared__ float Bs[2][BK][2 * BN];    // duplicated pairs: [k][2n..2n+1]

    int tid = threadIdx.x;
    size_t bm = (size_t)blockIdx.y * BM, bn = (size_t)blockIdx.x * BN;
    int tm = tid >> 4, tn = tid & 15;      // 16 x 16 thread grid

    // A ldg mapping: 2 threads per row, 8 floats each
    int ar = tid >> 1, ak = (tid & 1) * 8;
    const float* ag = A + (bm + (size_t)ar) * lda + ak;
    // B ldg mapping: 64 n-rows x 4 k-groups, 4 floats each
    int bi = tid & 63, bk = (tid >> 6) * 4;
    const float* bg = B + (bn + (size_t)bi) * ldb + bk;

    ull acc[4][4];
    #pragma unroll
    for (int q = 0; q < 4; q++)
        #pragma unroll
        for (int p = 0; p < 4; p++) acc[q][p] = 0ULL;

    float a0[4], a1[4], bb[4];

    // prologue: load + stage chunk 0
    *(float4*)a0 = *(const float4*)(ag);
    *(float4*)a1 = *(const float4*)(ag + 4);
    *(float4*)bb = *(const float4*)(bg);
    #pragma unroll
    for (int j = 0; j < 4; j++) {
        As[0][ak + j][ar]     = a0[j];
        As[0][ak + 4 + j][ar] = a1[j];
        *(float2*)&Bs[0][bk + j][2 * bi] = make_float2(bb[j], bb[j]);
    }
    __syncthreads();

    for (int i = 0; i < nchunks; i++) {
        int cb = i & 1;
        bool pf = (i + 1 < nchunks);
        if (pf) {
            const float* agp = ag + (size_t)(i + 1) * BK;
            const float* bgp = bg + (size_t)(i + 1) * BK;
            *(float4*)a0 = *(const float4*)(agp);
            *(float4*)a1 = *(const float4*)(agp + 4);
            *(float4*)bb = *(const float4*)(bgp);
        }

        #pragma unroll
        for (int k = 0; k < BK; k++) {
            ull ap[4], bd[4];
            #pragma unroll
            for (int p = 0; p < 4; p++)
                ap[p] = *(const ull*)&As[cb][k][tm * 8 + 2 * p];
            #pragma unroll
            for (int q = 0; q < 4; q++)
                bd[q] = *(const ull*)&Bs[cb][k][(tn * 4 + q) * 2];
            #pragma unroll
            for (int q = 0; q < 4; q++)
                #pragma unroll
                for (int p = 0; p < 4; p++)
                    FMA2(acc[q][p], ap[p], bd[q]);
        }

        if (pf) {
            int nb = cb ^ 1;
            #pragma unroll
            for (int j = 0; j < 4; j++) {
                As[nb][ak + j][ar]     = a0[j];
                As[nb][ak + 4 + j][ar] = a1[j];
                *(float2*)&Bs[nb][bk + j][2 * bi] = make_float2(bb[j], bb[j]);
            }
        }
        __syncthreads();
    }

    // ---- epilogue: 8 rows x 4 cols per thread ----
    size_t cb0 = bn + (size_t)tn * 4;
    #pragma unroll
    for (int rr = 0; rr < 8; rr++) {
        int p = rr >> 1, h = rr & 1;
        size_t row = bm + (size_t)tm * 8 + rr;
        float4 v;
        v.x = h ? f2hi(acc[0][p]) : f2lo(acc[0][p]);
        v.y = h ? f2hi(acc[1][p]) : f2lo(acc[1][p]);
        v.z = h ? f2hi(acc[2][p]) : f2lo(acc[2][p]);
        v.w = h ? f2hi(acc[3][p]) : f2lo(acc[3][p]);
        if (mode == 1) {
            *(float4*)(g_S + row * NLATP + cb0) = v;
        } else {
            int first;
            if (g_is64) first = (int)((const long long*)xv)[row * CHARS];
            else        first = ((const int*)xv)[row * CHARS];
            float* dst = out + row * DIM + cb0;
            if (first < 4) {
                *(float4*)dst = *(const float4*)(ce + (size_t)first * DIM + cb0);
            } else {
                const float4 e = *(const float4*)(g_E + row * DIM + cb0);
                v.x += e.x; v.y += e.y; v.z += e.z; v.w += e.w;
                *(float4*)dst = v;
            }
        }
    }
}

// ---------------- launch ----------------
extern "C" void kernel_launch(void* const* d_in, const int* in_sizes, int n_in,
                              void* d_out, int out_size) {
    const void*  x  = d_in[0];
    const float* ce = (const float*)d_in[1];
    const float* lm = (const float*)d_in[2];
    float* out = (float*)d_out;

    detect_kernel<<<1, 32>>>((const int*)x);
    conv_latent_kernel<<<(NLATP * DIM + 255) / 256, 256>>>(lm);
    {
        dim3 blk(32, 8), grd(NLATP / 32, DIM / 32);
        transpose_latent_kernel<<<grd, blk>>>(lm);
    }
    embed_kernel<<<NROWS, 256>>>(x, ce);

    // GEMM1: scores = E[16384,768] * Lf[5120,768]^T
    {
        dim3 grid(NLATP / BN, NROWS / BM);
        gemm_f32<<<grid, 256>>>(g_E, (size_t)DIM, g_Lf, (size_t)DIM,
                                DIM / BK, 1, x, ce, nullptr);
    }

    softmax_kernel<<<NROWS, 256>>>();

    // GEMM2 (+fused epilogue): out = E + D[16384,5120] * LTf[768,5120]^T
    {
        dim3 grid(DIM / BN, NROWS / BM);
        gemm_f32<<<grid, 256>>>(g_D, (size_t)NLATP, g_LTf, (size_t)NLATP,
                                NLATP / BK, 2, x, ce, out);
    }
}